// round 3
// baseline (speedup 1.0000x reference)
#include <cuda_runtime.h>
#include <math.h>

#define NND 100000
#define D 128
#define NELEM (NND*D)

// Scratch (allocation-free): two ping-pong feature buffers + LN reduction scalars.
__device__ float  g_buf0[NELEM];
__device__ float  g_buf1[NELEM];
__device__ double g_sum[3];
__device__ double g_sumsq[3];

#define PACK2(d, f)  asm("mov.b64 %0, {%1, %1};" : "=l"(d) : "f"(f))
#define UNPACK2(lo, hi, d) asm("mov.b64 {%0, %1}, %2;" : "=f"(lo), "=f"(hi) : "l"(d))
#define FMA2(d, a, b) asm("fma.rn.f32x2 %0, %1, %2, %3;" : "=l"(d) : "l"(a), "l"(b), "l"(d))

// h = (1+eps)*node ; also zero the LN accumulators for this replay.
__global__ void k_init(const float* __restrict__ node, const float* __restrict__ eps_p,
                       float* __restrict__ h) {
    long long i = blockIdx.x * (long long)blockDim.x + threadIdx.x;
    if (i == 0) {
        #pragma unroll
        for (int j = 0; j < 3; ++j) { g_sum[j] = 0.0; g_sumsq[j] = 0.0; }
    }
    if (i < NELEM/4) {
        float s = 1.0f + eps_p[0];
        float4 v = __ldg((const float4*)node + i);
        v.x *= s; v.y *= s; v.z *= s; v.w *= s;
        ((float4*)h)[i] = v;
    }
}

// One warp per edge: gather node[src] row (32 x float4), vector-red into h[dst].
__global__ void k_scatter(const float* __restrict__ node, const int* __restrict__ ei,
                          float* __restrict__ h, int E) {
    long long gid = blockIdx.x * (long long)blockDim.x + threadIdx.x;
    int e    = (int)(gid >> 5);
    int lane = (int)(gid & 31);
    if (e >= E) return;
    int src = __ldg(ei + e);
    int dst = __ldg(ei + E + e);
    float4 v = __ldg((const float4*)node + (long long)src * 32 + lane);
    float* d = h + (long long)dst * D + lane * 4;
    asm volatile("red.global.add.v4.f32 [%0], {%1,%2,%3,%4};"
                 :: "l"(d), "f"(v.x), "f"(v.y), "f"(v.z), "f"(v.w) : "memory");
}

// ---------------- GEMM ----------------
// Y = op(A) @ W + bias ; op = identity or relu(graph_ln(A)).
// 128x128 tile, 256 threads, 8x8 micro-tile, FFMA2 accumulation.
// B tile is pre-duplicated into packed (b,b) 64-bit pairs in smem so the
// inner loop is pure LDS.128 + FFMA2 (no mov.b64 in the hot path).
template<bool APPLY>
__global__ void __launch_bounds__(256)
k_gemm(const float* __restrict__ A, const float* __restrict__ W,
       const float* __restrict__ bias,
       const float* __restrict__ lnw, const float* __restrict__ lnb,
       int sidx_in, int sidx_out,
       float* __restrict__ Y, int M)
{
    __shared__ float As[16][132];
    __shared__ unsigned long long Bs2[16][128];
    __shared__ float s_bias[128];
    __shared__ float s_lnw[128];
    __shared__ float s_lnb[128];

    const int t  = threadIdx.x;
    const int tx = t & 15;
    const int ty = t >> 4;
    const int row0 = blockIdx.x * 128;

    if (t < 128) {
        s_bias[t] = bias[t];
        if (APPLY) { s_lnw[t] = lnw[t]; s_lnb[t] = lnb[t]; }
    }
    float mu = 0.f, inv = 0.f;
    if (APPLY) {
        double m = g_sum[sidx_in] * (1.0 / (double)NELEM);
        double v = g_sumsq[sidx_in] * (1.0 / (double)NELEM) - m * m;
        if (v < 0.0) v = 0.0;
        mu  = (float)m;
        inv = 1.0f / (sqrtf((float)v) + 1e-5f);
    }
    __syncthreads();

    unsigned long long acc[4][8];
    #pragma unroll
    for (int i = 0; i < 4; ++i)
        #pragma unroll
        for (int j = 0; j < 8; ++j) acc[i][j] = 0ULL;

    for (int kb = 0; kb < 128; kb += 16) {
        // A tile, LN+ReLU fused, transposed store.
        #pragma unroll
        for (int it = 0; it < 2; ++it) {
            int idx = t + it * 256;
            int r   = idx >> 2;
            int c4  = idx & 3;
            int grow = row0 + r;
            float4 v = make_float4(0.f, 0.f, 0.f, 0.f);
            if (grow < M) v = __ldg((const float4*)(A + (long long)grow * D + kb) + c4);
            if (APPLY) {
                int k0 = kb + c4 * 4;
                v.x = fmaxf((v.x - mu) * inv * s_lnw[k0+0] + s_lnb[k0+0], 0.f);
                v.y = fmaxf((v.y - mu) * inv * s_lnw[k0+1] + s_lnb[k0+1], 0.f);
                v.z = fmaxf((v.z - mu) * inv * s_lnw[k0+2] + s_lnb[k0+2], 0.f);
                v.w = fmaxf((v.w - mu) * inv * s_lnw[k0+3] + s_lnb[k0+3], 0.f);
            }
            As[c4*4+0][r] = v.x;
            As[c4*4+1][r] = v.y;
            As[c4*4+2][r] = v.z;
            As[c4*4+3][r] = v.w;
        }
        // B tile, duplicated into (b,b) pairs at store time.
        #pragma unroll
        for (int it = 0; it < 2; ++it) {
            int idx = t + it * 256;
            int kr  = idx >> 5;
            int c4  = idx & 31;
            float4 v = __ldg((const float4*)(W + (long long)(kb + kr) * D) + c4);
            unsigned long long d0, d1, d2, d3;
            PACK2(d0, v.x); PACK2(d1, v.y); PACK2(d2, v.z); PACK2(d3, v.w);
            ulonglong2* dp = (ulonglong2*)&Bs2[kr][c4 * 4];
            dp[0] = make_ulonglong2(d0, d1);
            dp[1] = make_ulonglong2(d2, d3);
        }
        __syncthreads();

        #pragma unroll
        for (int k = 0; k < 16; ++k) {
            const ulonglong2* ap = (const ulonglong2*)&As[k][ty * 8];
            ulonglong2 a01 = ap[0], a23 = ap[1];
            const ulonglong2* bpA = (const ulonglong2*)&Bs2[k][tx * 4];
            const ulonglong2* bpB = (const ulonglong2*)&Bs2[k][64 + tx * 4];
            ulonglong2 b01 = bpA[0], b23 = bpA[1];
            ulonglong2 b45 = bpB[0], b67 = bpB[1];
            unsigned long long bd[8] = {b01.x, b01.y, b23.x, b23.y,
                                        b45.x, b45.y, b67.x, b67.y};
            #pragma unroll
            for (int j = 0; j < 8; ++j) {
                FMA2(acc[0][j], a01.x, bd[j]);
                FMA2(acc[1][j], a01.y, bd[j]);
                FMA2(acc[2][j], a23.x, bd[j]);
                FMA2(acc[3][j], a23.y, bd[j]);
            }
        }
        __syncthreads();
    }

    // Epilogue: bias, store, LN partial sums.
    float lsum = 0.f, lsq = 0.f;
    #pragma unroll
    for (int ri = 0; ri < 4; ++ri) {
        float lo[8], hi[8];
        #pragma unroll
        for (int j = 0; j < 8; ++j) UNPACK2(lo[j], hi[j], acc[ri][j]);
        #pragma unroll
        for (int p = 0; p < 2; ++p) {
            int grow = row0 + ty * 8 + ri * 2 + p;
            if (grow < M) {
                float c[8];
                #pragma unroll
                for (int j = 0; j < 8; ++j) {
                    int col = (j < 4) ? (tx * 4 + j) : (64 + tx * 4 + j - 4);
                    float val = (p == 0 ? lo[j] : hi[j]) + s_bias[col];
                    c[j] = val;
                    lsum += val;
                    lsq  += val * val;
                }
                *(float4*)(Y + (long long)grow * D + tx * 4)      = make_float4(c[0], c[1], c[2], c[3]);
                *(float4*)(Y + (long long)grow * D + 64 + tx * 4) = make_float4(c[4], c[5], c[6], c[7]);
            }
        }
    }
    #pragma unroll
    for (int o = 16; o > 0; o >>= 1) {
        lsum += __shfl_down_sync(0xffffffffu, lsum, o);
        lsq  += __shfl_down_sync(0xffffffffu, lsq, o);
    }
    if ((t & 31) == 0) {
        atomicAdd(&g_sum[sidx_out],   (double)lsum);
        atomicAdd(&g_sumsq[sidx_out], (double)lsq);
    }
}

// out = relu(graph_layernorm(Y)), sums at index 2.
__global__ void k_apply_out(const float* __restrict__ Y, const float* __restrict__ w,
                            const float* __restrict__ b, float* __restrict__ out) {
    long long i = blockIdx.x * (long long)blockDim.x + threadIdx.x;
    if (i >= NELEM/4) return;
    double m = g_sum[2] * (1.0 / (double)NELEM);
    double v = g_sumsq[2] * (1.0 / (double)NELEM) - m * m;
    if (v < 0.0) v = 0.0;
    float mu  = (float)m;
    float inv = 1.0f / (sqrtf((float)v) + 1e-5f);
    int k = ((int)i * 4) & 127;
    float4 val = __ldg((const float4*)Y + i);
    float4 o;
    o.x = fmaxf((val.x - mu) * inv * __ldg(w + k + 0) + __ldg(b + k + 0), 0.f);
    o.y = fmaxf((val.y - mu) * inv * __ldg(w + k + 1) + __ldg(b + k + 1), 0.f);
    o.z = fmaxf((val.z - mu) * inv * __ldg(w + k + 2) + __ldg(b + k + 2), 0.f);
    o.w = fmaxf((val.w - mu) * inv * __ldg(w + k + 3) + __ldg(b + k + 3), 0.f);
    ((float4*)out)[i] = o;
}

extern "C" void kernel_launch(void* const* d_in, const int* in_sizes, int n_in,
                              void* d_out, int out_size) {
    const float* node = (const float*)d_in[0];
    const int*   ei   = (const int*)d_in[1];
    const float* eps  = (const float*)d_in[4];
    const float* W1   = (const float*)d_in[5];
    const float* b1   = (const float*)d_in[6];
    const float* ln1w = (const float*)d_in[7];
    const float* ln1b = (const float*)d_in[8];
    const float* W2   = (const float*)d_in[9];
    const float* b2   = (const float*)d_in[10];
    const float* ln2w = (const float*)d_in[11];
    const float* ln2b = (const float*)d_in[12];
    const float* W3   = (const float*)d_in[13];
    const float* b3   = (const float*)d_in[14];
    const float* lnow = (const float*)d_in[15];
    const float* lnob = (const float*)d_in[16];

    int E = in_sizes[1] / 2;

    void *p0, *p1;
    cudaGetSymbolAddress(&p0, g_buf0);
    cudaGetSymbolAddress(&p1, g_buf1);
    float* buf0 = (float*)p0;
    float* buf1 = (float*)p1;

    int nb_elem = (NELEM/4 + 255) / 256;
    k_init<<<nb_elem, 256>>>(node, eps, buf0);

    long long sthreads = (long long)E * 32;
    int sblocks = (int)((sthreads + 255) / 256);
    k_scatter<<<sblocks, 256>>>(node, ei, buf0, E);

    int gblocks = (NND + 127) / 128;
    k_gemm<false><<<gblocks, 256>>>(buf0, W1, b1, nullptr, nullptr, 0, 0, buf1, NND);
    k_gemm<true> <<<gblocks, 256>>>(buf1, W2, b2, ln1w, ln1b, 0, 1, buf0, NND);
    k_gemm<true> <<<gblocks, 256>>>(buf0, W3, b3, ln2w, ln2b, 1, 2, buf1, NND);

    k_apply_out<<<nb_elem, 256>>>(buf1, lnow, lnob, (float*)d_out);
}

// round 4
// speedup vs baseline: 1.3208x; 1.3208x over previous
#include <cuda_runtime.h>
#include <math.h>

#define NND 100000
#define D 128
#define NELEM (NND*D)
#define EMAX 2000000
#define NBLK 98           // ceil(100000/1024)

// Scratch (allocation-free)
__device__ float  g_buf0[NELEM];
__device__ float  g_buf1[NELEM];
__device__ double g_sum[3];
__device__ double g_sumsq[3];
__device__ int    g_deg[NND + 1];
__device__ int    g_off[NND + 1];
__device__ int    g_cursor[NND];
__device__ int    g_srcs[EMAX];
__device__ int    g_blocksum[128];
__device__ int    g_blockoff[128];

#define PACK2(d, f)  asm("mov.b64 %0, {%1, %1};" : "=l"(d) : "f"(f))
#define UNPACK2(lo, hi, d) asm("mov.b64 {%0, %1}, %2;" : "=f"(lo), "=f"(hi) : "l"(d))
#define FMA2(d, a, b) asm("fma.rn.f32x2 %0, %1, %2, %3;" : "=l"(d) : "l"(a), "l"(b), "l"(d))

// ---------------- CSR build ----------------

__global__ void k_zero() {
    int i = blockIdx.x * blockDim.x + threadIdx.x;
    if (i <= NND) g_deg[i] = 0;
    if (i < 3) { g_sum[i] = 0.0; g_sumsq[i] = 0.0; }
}

__global__ void k_count(const int* __restrict__ ei, int E) {
    int e = blockIdx.x * blockDim.x + threadIdx.x;
    if (e < E) atomicAdd(&g_deg[__ldg(ei + E + e)], 1);
}

__global__ void __launch_bounds__(1024) k_scan1() {
    __shared__ int s[1024];
    int t = threadIdx.x;
    int i = blockIdx.x * 1024 + t;
    int v = (i < NND) ? g_deg[i] : 0;
    s[t] = v;
    __syncthreads();
    #pragma unroll
    for (int o = 1; o < 1024; o <<= 1) {
        int add = (t >= o) ? s[t - o] : 0;
        __syncthreads();
        s[t] += add;
        __syncthreads();
    }
    if (i <= NND) g_off[i] = s[t] - v;   // exclusive within block
    if (t == 1023) g_blocksum[blockIdx.x] = s[t];
}

__global__ void __launch_bounds__(128) k_scan2() {
    __shared__ int s[128];
    int t = threadIdx.x;
    int v = (t < NBLK) ? g_blocksum[t] : 0;
    s[t] = v;
    __syncthreads();
    #pragma unroll
    for (int o = 1; o < 128; o <<= 1) {
        int add = (t >= o) ? s[t - o] : 0;
        __syncthreads();
        s[t] += add;
        __syncthreads();
    }
    g_blockoff[t] = s[t] - v;            // exclusive block offsets
}

__global__ void k_scan3(int E) {
    int i = blockIdx.x * blockDim.x + threadIdx.x;
    if (i < NND) {
        int off = g_off[i] + g_blockoff[i >> 10];
        g_off[i] = off;
        g_cursor[i] = off;
    }
    if (i == 0) g_off[NND] = E;
}

__global__ void k_fill(const int* __restrict__ ei, int E) {
    int e = blockIdx.x * blockDim.x + threadIdx.x;
    if (e >= E) return;
    int dst = __ldg(ei + E + e);
    int src = __ldg(ei + e);
    int pos = atomicAdd(&g_cursor[dst], 1);
    g_srcs[pos] = src;
}

// h[n] = (1+eps)*node[n] + sum_{e: dst=n} node[src[e]]. Warp per node.
__global__ void __launch_bounds__(256) k_aggr(const float* __restrict__ node,
                                              const float* __restrict__ eps_p,
                                              float* __restrict__ h) {
    int warp = (blockIdx.x * blockDim.x + threadIdx.x) >> 5;
    int lane = threadIdx.x & 31;
    if (warp >= NND) return;
    int n = warp;
    float s = 1.0f + __ldg(eps_p);
    const float4* nodes = (const float4*)node;
    float4 acc = __ldg(nodes + (long long)n * 32 + lane);
    acc.x *= s; acc.y *= s; acc.z *= s; acc.w *= s;
    int j   = g_off[n];
    int end = g_off[n + 1];
    for (; j + 4 <= end; j += 4) {
        int s0 = __ldg(&g_srcs[j + 0]);
        int s1 = __ldg(&g_srcs[j + 1]);
        int s2 = __ldg(&g_srcs[j + 2]);
        int s3 = __ldg(&g_srcs[j + 3]);
        float4 v0 = __ldg(nodes + (long long)s0 * 32 + lane);
        float4 v1 = __ldg(nodes + (long long)s1 * 32 + lane);
        float4 v2 = __ldg(nodes + (long long)s2 * 32 + lane);
        float4 v3 = __ldg(nodes + (long long)s3 * 32 + lane);
        acc.x += v0.x + v1.x + v2.x + v3.x;
        acc.y += v0.y + v1.y + v2.y + v3.y;
        acc.z += v0.z + v1.z + v2.z + v3.z;
        acc.w += v0.w + v1.w + v2.w + v3.w;
    }
    for (; j < end; ++j) {
        int s0 = __ldg(&g_srcs[j]);
        float4 v0 = __ldg(nodes + (long long)s0 * 32 + lane);
        acc.x += v0.x; acc.y += v0.y; acc.z += v0.z; acc.w += v0.w;
    }
    ((float4*)h)[(long long)n * 32 + lane] = acc;
}

// ---------------- GEMM ----------------
// Y = op(A) @ W + bias ; op = identity or relu(graph_ln(A)).
// 128x128 tile, 256 threads, 8x8 micro-tile, FFMA2 accumulation.
// B pre-duplicated into packed (b,b) pairs in smem; inner loop consumes the
// ulonglong2 pairs directly (no copy array). __launch_bounds__(256,2) caps
// regs at 128 so 2 blocks/SM fit the regfile.
template<bool APPLY>
__global__ void __launch_bounds__(256, 2)
k_gemm(const float* __restrict__ A, const float* __restrict__ W,
       const float* __restrict__ bias,
       const float* __restrict__ lnw, const float* __restrict__ lnb,
       int sidx_in, int sidx_out,
       float* __restrict__ Y, int M)
{
    __shared__ float As[16][132];
    __shared__ unsigned long long Bs2[16][128];
    __shared__ float s_bias[128];
    __shared__ float s_lnw[128];
    __shared__ float s_lnb[128];

    const int t  = threadIdx.x;
    const int tx = t & 15;
    const int ty = t >> 4;
    const int row0 = blockIdx.x * 128;

    if (t < 128) {
        s_bias[t] = bias[t];
        if (APPLY) { s_lnw[t] = lnw[t]; s_lnb[t] = lnb[t]; }
    }
    float mu = 0.f, inv = 0.f;
    if (APPLY) {
        double m = g_sum[sidx_in] * (1.0 / (double)NELEM);
        double v = g_sumsq[sidx_in] * (1.0 / (double)NELEM) - m * m;
        if (v < 0.0) v = 0.0;
        mu  = (float)m;
        inv = 1.0f / (sqrtf((float)v) + 1e-5f);
    }
    __syncthreads();

    unsigned long long acc[4][8];
    #pragma unroll
    for (int i = 0; i < 4; ++i)
        #pragma unroll
        for (int j = 0; j < 8; ++j) acc[i][j] = 0ULL;

    for (int kb = 0; kb < 128; kb += 16) {
        // A tile, LN+ReLU fused, transposed store.
        #pragma unroll
        for (int it = 0; it < 2; ++it) {
            int idx = t + it * 256;
            int r   = idx >> 2;
            int c4  = idx & 3;
            int grow = row0 + r;
            float4 v = make_float4(0.f, 0.f, 0.f, 0.f);
            if (grow < M) v = __ldg((const float4*)(A + (long long)grow * D + kb) + c4);
            if (APPLY) {
                int k0 = kb + c4 * 4;
                v.x = fmaxf((v.x - mu) * inv * s_lnw[k0+0] + s_lnb[k0+0], 0.f);
                v.y = fmaxf((v.y - mu) * inv * s_lnw[k0+1] + s_lnb[k0+1], 0.f);
                v.z = fmaxf((v.z - mu) * inv * s_lnw[k0+2] + s_lnb[k0+2], 0.f);
                v.w = fmaxf((v.w - mu) * inv * s_lnw[k0+3] + s_lnb[k0+3], 0.f);
            }
            As[c4*4+0][r] = v.x;
            As[c4*4+1][r] = v.y;
            As[c4*4+2][r] = v.z;
            As[c4*4+3][r] = v.w;
        }
        // B tile, duplicated into (b,b) pairs at store time.
        #pragma unroll
        for (int it = 0; it < 2; ++it) {
            int idx = t + it * 256;
            int kr  = idx >> 5;
            int c4  = idx & 31;
            float4 v = __ldg((const float4*)(W + (long long)(kb + kr) * D) + c4);
            unsigned long long d0, d1, d2, d3;
            PACK2(d0, v.x); PACK2(d1, v.y); PACK2(d2, v.z); PACK2(d3, v.w);
            ulonglong2* dp = (ulonglong2*)&Bs2[kr][c4 * 4];
            dp[0] = make_ulonglong2(d0, d1);
            dp[1] = make_ulonglong2(d2, d3);
        }
        __syncthreads();

        #pragma unroll
        for (int k = 0; k < 16; ++k) {
            const ulonglong2* ap = (const ulonglong2*)&As[k][ty * 8];
            ulonglong2 a01 = ap[0], a23 = ap[1];
            const ulonglong2* bpA = (const ulonglong2*)&Bs2[k][tx * 4];
            const ulonglong2* bpB = (const ulonglong2*)&Bs2[k][64 + tx * 4];
            {
                ulonglong2 b = bpA[0];
                FMA2(acc[0][0], a01.x, b.x); FMA2(acc[1][0], a01.y, b.x);
                FMA2(acc[2][0], a23.x, b.x); FMA2(acc[3][0], a23.y, b.x);
                FMA2(acc[0][1], a01.x, b.y); FMA2(acc[1][1], a01.y, b.y);
                FMA2(acc[2][1], a23.x, b.y); FMA2(acc[3][1], a23.y, b.y);
            }
            {
                ulonglong2 b = bpA[1];
                FMA2(acc[0][2], a01.x, b.x); FMA2(acc[1][2], a01.y, b.x);
                FMA2(acc[2][2], a23.x, b.x); FMA2(acc[3][2], a23.y, b.x);
                FMA2(acc[0][3], a01.x, b.y); FMA2(acc[1][3], a01.y, b.y);
                FMA2(acc[2][3], a23.x, b.y); FMA2(acc[3][3], a23.y, b.y);
            }
            {
                ulonglong2 b = bpB[0];
                FMA2(acc[0][4], a01.x, b.x); FMA2(acc[1][4], a01.y, b.x);
                FMA2(acc[2][4], a23.x, b.x); FMA2(acc[3][4], a23.y, b.x);
                FMA2(acc[0][5], a01.x, b.y); FMA2(acc[1][5], a01.y, b.y);
                FMA2(acc[2][5], a23.x, b.y); FMA2(acc[3][5], a23.y, b.y);
            }
            {
                ulonglong2 b = bpB[1];
                FMA2(acc[0][6], a01.x, b.x); FMA2(acc[1][6], a01.y, b.x);
                FMA2(acc[2][6], a23.x, b.x); FMA2(acc[3][6], a23.y, b.x);
                FMA2(acc[0][7], a01.x, b.y); FMA2(acc[1][7], a01.y, b.y);
                FMA2(acc[2][7], a23.x, b.y); FMA2(acc[3][7], a23.y, b.y);
            }
        }
        __syncthreads();
    }

    // Epilogue: bias, store, LN partial sums.
    float lsum = 0.f, lsq = 0.f;
    #pragma unroll
    for (int ri = 0; ri < 4; ++ri) {
        float lo[8], hi[8];
        #pragma unroll
        for (int j = 0; j < 8; ++j) UNPACK2(lo[j], hi[j], acc[ri][j]);
        #pragma unroll
        for (int p = 0; p < 2; ++p) {
            int grow = row0 + ty * 8 + ri * 2 + p;
            if (grow < M) {
                float c[8];
                #pragma unroll
                for (int j = 0; j < 8; ++j) {
                    int col = (j < 4) ? (tx * 4 + j) : (64 + tx * 4 + j - 4);
                    float val = (p == 0 ? lo[j] : hi[j]) + s_bias[col];
                    c[j] = val;
                    lsum += val;
                    lsq  += val * val;
                }
                *(float4*)(Y + (long long)grow * D + tx * 4)      = make_float4(c[0], c[1], c[2], c[3]);
                *(float4*)(Y + (long long)grow * D + 64 + tx * 4) = make_float4(c[4], c[5], c[6], c[7]);
            }
        }
    }
    #pragma unroll
    for (int o = 16; o > 0; o >>= 1) {
        lsum += __shfl_down_sync(0xffffffffu, lsum, o);
        lsq  += __shfl_down_sync(0xffffffffu, lsq, o);
    }
    if ((t & 31) == 0) {
        atomicAdd(&g_sum[sidx_out],   (double)lsum);
        atomicAdd(&g_sumsq[sidx_out], (double)lsq);
    }
}

// out = relu(graph_layernorm(Y)), sums at index 2.
__global__ void k_apply_out(const float* __restrict__ Y, const float* __restrict__ w,
                            const float* __restrict__ b, float* __restrict__ out) {
    long long i = blockIdx.x * (long long)blockDim.x + threadIdx.x;
    if (i >= NELEM/4) return;
    double m = g_sum[2] * (1.0 / (double)NELEM);
    double v = g_sumsq[2] * (1.0 / (double)NELEM) - m * m;
    if (v < 0.0) v = 0.0;
    float mu  = (float)m;
    float inv = 1.0f / (sqrtf((float)v) + 1e-5f);
    int k = ((int)i * 4) & 127;
    float4 val = __ldg((const float4*)Y + i);
    float4 o;
    o.x = fmaxf((val.x - mu) * inv * __ldg(w + k + 0) + __ldg(b + k + 0), 0.f);
    o.y = fmaxf((val.y - mu) * inv * __ldg(w + k + 1) + __ldg(b + k + 1), 0.f);
    o.z = fmaxf((val.z - mu) * inv * __ldg(w + k + 2) + __ldg(b + k + 2), 0.f);
    o.w = fmaxf((val.w - mu) * inv * __ldg(w + k + 3) + __ldg(b + k + 3), 0.f);
    ((float4*)out)[i] = o;
}

extern "C" void kernel_launch(void* const* d_in, const int* in_sizes, int n_in,
                              void* d_out, int out_size) {
    const float* node = (const float*)d_in[0];
    const int*   ei   = (const int*)d_in[1];
    const float* eps  = (const float*)d_in[4];
    const float* W1   = (const float*)d_in[5];
    const float* b1   = (const float*)d_in[6];
    const float* ln1w = (const float*)d_in[7];
    const float* ln1b = (const float*)d_in[8];
    const float* W2   = (const float*)d_in[9];
    const float* b2   = (const float*)d_in[10];
    const float* ln2w = (const float*)d_in[11];
    const float* ln2b = (const float*)d_in[12];
    const float* W3   = (const float*)d_in[13];
    const float* b3   = (const float*)d_in[14];
    const float* lnow = (const float*)d_in[15];
    const float* lnob = (const float*)d_in[16];

    int E = in_sizes[1] / 2;

    void *p0, *p1;
    cudaGetSymbolAddress(&p0, g_buf0);
    cudaGetSymbolAddress(&p1, g_buf1);
    float* buf0 = (float*)p0;
    float* buf1 = (float*)p1;

    // CSR build
    k_zero<<<(NND + 1024) / 1024, 1024>>>();
    k_count<<<(E + 255) / 256, 256>>>(ei, E);
    k_scan1<<<NBLK, 1024>>>();
    k_scan2<<<1, 128>>>();
    k_scan3<<<(NND + 255) / 256, 256>>>(E);
    k_fill<<<(E + 255) / 256, 256>>>(ei, E);

    // Aggregation: h = (1+eps)*node + gather-sum
    k_aggr<<<(NND * 32 + 255) / 256, 256>>>(node, eps, buf0);

    int gblocks = (NND + 127) / 128;
    k_gemm<false><<<gblocks, 256>>>(buf0, W1, b1, nullptr, nullptr, 0, 0, buf1, NND);
    k_gemm<true> <<<gblocks, 256>>>(buf1, W2, b2, ln1w, ln1b, 0, 1, buf0, NND);
    k_gemm<true> <<<gblocks, 256>>>(buf0, W3, b3, ln2w, ln2b, 1, 2, buf1, NND);

    int nb_elem = (NELEM/4 + 255) / 256;
    k_apply_out<<<nb_elem, 256>>>(buf1, lnow, lnob, (float*)d_out);
}

// round 5
// speedup vs baseline: 1.9430x; 1.4711x over previous
#include <cuda_runtime.h>
#include <math.h>

#define NND 100000
#define D 128
#define NELEM (NND*D)
#define EMAX 2000000
#define NBLK 98           // ceil(100000/1024)

// Scratch (allocation-free)
__device__ float  g_buf0[NELEM];
__device__ float  g_buf1[NELEM];
__device__ double g_sum[3];
__device__ double g_sumsq[3];
__device__ int    g_deg[NND + 1];
__device__ int    g_off[NND + 1];
__device__ int    g_cursor[NND];
__device__ int    g_srcs[EMAX];
__device__ int    g_blocksum[128];
__device__ int    g_blockoff[128];

#define PACK2(d, f)  asm("mov.b64 %0, {%1, %1};" : "=l"(d) : "f"(f))
#define UNPACK2(lo, hi, d) asm("mov.b64 {%0, %1}, %2;" : "=f"(lo), "=f"(hi) : "l"(d))
#define FMA2(d, a, b) asm("fma.rn.f32x2 %0, %1, %2, %3;" : "=l"(d) : "l"(a), "l"(b), "l"(d))

// ---------------- CSR build ----------------

__global__ void k_zero() {
    int i = blockIdx.x * blockDim.x + threadIdx.x;
    if (i <= NND) g_deg[i] = 0;
    if (i < 3) { g_sum[i] = 0.0; g_sumsq[i] = 0.0; }
}

__global__ void k_count(const int* __restrict__ ei, int E) {
    int e = blockIdx.x * blockDim.x + threadIdx.x;
    if (e < E) atomicAdd(&g_deg[__ldg(ei + E + e)], 1);
}

__global__ void __launch_bounds__(1024) k_scan1() {
    __shared__ int s[1024];
    int t = threadIdx.x;
    int i = blockIdx.x * 1024 + t;
    int v = (i < NND) ? g_deg[i] : 0;
    s[t] = v;
    __syncthreads();
    #pragma unroll
    for (int o = 1; o < 1024; o <<= 1) {
        int add = (t >= o) ? s[t - o] : 0;
        __syncthreads();
        s[t] += add;
        __syncthreads();
    }
    if (i <= NND) g_off[i] = s[t] - v;   // exclusive within block
    if (t == 1023) g_blocksum[blockIdx.x] = s[t];
}

__global__ void __launch_bounds__(128) k_scan2() {
    __shared__ int s[128];
    int t = threadIdx.x;
    int v = (t < NBLK) ? g_blocksum[t] : 0;
    s[t] = v;
    __syncthreads();
    #pragma unroll
    for (int o = 1; o < 128; o <<= 1) {
        int add = (t >= o) ? s[t - o] : 0;
        __syncthreads();
        s[t] += add;
        __syncthreads();
    }
    g_blockoff[t] = s[t] - v;            // exclusive block offsets
}

__global__ void k_scan3(int E) {
    int i = blockIdx.x * blockDim.x + threadIdx.x;
    if (i < NND) {
        int off = g_off[i] + g_blockoff[i >> 10];
        g_off[i] = off;
        g_cursor[i] = off;
    }
    if (i == 0) g_off[NND] = E;
}

__global__ void k_fill(const int* __restrict__ ei, int E) {
    int e = blockIdx.x * blockDim.x + threadIdx.x;
    if (e >= E) return;
    int dst = __ldg(ei + E + e);
    int src = __ldg(ei + e);
    int pos = atomicAdd(&g_cursor[dst], 1);
    g_srcs[pos] = src;
}

// h[n] = (1+eps)*node[n] + sum_{e: dst=n} node[src[e]]. Warp per node.
__global__ void __launch_bounds__(256) k_aggr(const float* __restrict__ node,
                                              const float* __restrict__ eps_p,
                                              float* __restrict__ h) {
    int warp = (blockIdx.x * blockDim.x + threadIdx.x) >> 5;
    int lane = threadIdx.x & 31;
    if (warp >= NND) return;
    int n = warp;
    float s = 1.0f + __ldg(eps_p);
    const float4* nodes = (const float4*)node;
    float4 acc = __ldg(nodes + (long long)n * 32 + lane);
    acc.x *= s; acc.y *= s; acc.z *= s; acc.w *= s;
    int j   = g_off[n];
    int end = g_off[n + 1];
    for (; j + 4 <= end; j += 4) {
        int s0 = __ldg(&g_srcs[j + 0]);
        int s1 = __ldg(&g_srcs[j + 1]);
        int s2 = __ldg(&g_srcs[j + 2]);
        int s3 = __ldg(&g_srcs[j + 3]);
        float4 v0 = __ldg(nodes + (long long)s0 * 32 + lane);
        float4 v1 = __ldg(nodes + (long long)s1 * 32 + lane);
        float4 v2 = __ldg(nodes + (long long)s2 * 32 + lane);
        float4 v3 = __ldg(nodes + (long long)s3 * 32 + lane);
        acc.x += v0.x + v1.x + v2.x + v3.x;
        acc.y += v0.y + v1.y + v2.y + v3.y;
        acc.z += v0.z + v1.z + v2.z + v3.z;
        acc.w += v0.w + v1.w + v2.w + v3.w;
    }
    for (; j < end; ++j) {
        int s0 = __ldg(&g_srcs[j]);
        float4 v0 = __ldg(nodes + (long long)s0 * 32 + lane);
        acc.x += v0.x; acc.y += v0.y; acc.z += v0.z; acc.w += v0.w;
    }
    ((float4*)h)[(long long)n * 32 + lane] = acc;
}

// ---------------- GEMM (round-1 proven version, verbatim) ----------------
// Y = op(A) @ W + bias ; op = identity or relu(graph_ln(A)).
// 128x128 tile, 256 threads, 8x8 micro-tile, FFMA2 accumulation with
// per-k B duplication via PACK2 (122 regs -> 2 blocks/SM, 83 us measured).
template<bool APPLY>
__global__ void __launch_bounds__(256)
k_gemm(const float* __restrict__ A, const float* __restrict__ W,
       const float* __restrict__ bias,
       const float* __restrict__ lnw, const float* __restrict__ lnb,
       int sidx_in, int sidx_out,
       float* __restrict__ Y, int M)
{
    __shared__ float As[16][132];
    __shared__ float Bs[16][128];
    __shared__ float s_bias[128];
    __shared__ float s_lnw[128];
    __shared__ float s_lnb[128];

    const int t  = threadIdx.x;
    const int tx = t & 15;
    const int ty = t >> 4;
    const int row0 = blockIdx.x * 128;

    if (t < 128) {
        s_bias[t] = bias[t];
        if (APPLY) { s_lnw[t] = lnw[t]; s_lnb[t] = lnb[t]; }
    }
    float mu = 0.f, inv = 0.f;
    if (APPLY) {
        double m = g_sum[sidx_in] * (1.0 / (double)NELEM);
        double v = g_sumsq[sidx_in] * (1.0 / (double)NELEM) - m * m;
        if (v < 0.0) v = 0.0;
        mu  = (float)m;
        inv = 1.0f / (sqrtf((float)v) + 1e-5f);
    }
    __syncthreads();

    unsigned long long acc[4][8];
    #pragma unroll
    for (int i = 0; i < 4; ++i)
        #pragma unroll
        for (int j = 0; j < 8; ++j) acc[i][j] = 0ULL;

    for (int kb = 0; kb < 128; kb += 16) {
        // A tile, LN+ReLU fused, transposed store.
        #pragma unroll
        for (int it = 0; it < 2; ++it) {
            int idx = t + it * 256;
            int r   = idx >> 2;
            int c4  = idx & 3;
            int grow = row0 + r;
            float4 v = make_float4(0.f, 0.f, 0.f, 0.f);
            if (grow < M) v = __ldg((const float4*)(A + (long long)grow * D + kb) + c4);
            if (APPLY) {
                int k0 = kb + c4 * 4;
                v.x = fmaxf((v.x - mu) * inv * s_lnw[k0+0] + s_lnb[k0+0], 0.f);
                v.y = fmaxf((v.y - mu) * inv * s_lnw[k0+1] + s_lnb[k0+1], 0.f);
                v.z = fmaxf((v.z - mu) * inv * s_lnw[k0+2] + s_lnb[k0+2], 0.f);
                v.w = fmaxf((v.w - mu) * inv * s_lnw[k0+3] + s_lnb[k0+3], 0.f);
            }
            As[c4*4+0][r] = v.x;
            As[c4*4+1][r] = v.y;
            As[c4*4+2][r] = v.z;
            As[c4*4+3][r] = v.w;
        }
        // B tile (16 k x 128 cols).
        #pragma unroll
        for (int it = 0; it < 2; ++it) {
            int idx = t + it * 256;
            int kr  = idx >> 5;
            int c4  = idx & 31;
            float4 v = __ldg((const float4*)(W + (long long)(kb + kr) * D) + c4);
            *((float4*)&Bs[kr][0] + c4) = v;
        }
        __syncthreads();

        #pragma unroll
        for (int k = 0; k < 16; ++k) {
            const unsigned long long* ap = (const unsigned long long*)&As[k][ty * 8];
            unsigned long long a0 = ap[0], a1 = ap[1], a2 = ap[2], a3 = ap[3];
            float4 bA = *(const float4*)&Bs[k][tx * 4];
            float4 bB = *(const float4*)&Bs[k][64 + tx * 4];
            unsigned long long bd[8];
            PACK2(bd[0], bA.x); PACK2(bd[1], bA.y); PACK2(bd[2], bA.z); PACK2(bd[3], bA.w);
            PACK2(bd[4], bB.x); PACK2(bd[5], bB.y); PACK2(bd[6], bB.z); PACK2(bd[7], bB.w);
            #pragma unroll
            for (int j = 0; j < 8; ++j) {
                FMA2(acc[0][j], a0, bd[j]);
                FMA2(acc[1][j], a1, bd[j]);
                FMA2(acc[2][j], a2, bd[j]);
                FMA2(acc[3][j], a3, bd[j]);
            }
        }
        __syncthreads();
    }

    // Epilogue: bias, store, LN partial sums.
    float lsum = 0.f, lsq = 0.f;
    #pragma unroll
    for (int ri = 0; ri < 4; ++ri) {
        float lo[8], hi[8];
        #pragma unroll
        for (int j = 0; j < 8; ++j) UNPACK2(lo[j], hi[j], acc[ri][j]);
        #pragma unroll
        for (int p = 0; p < 2; ++p) {
            int grow = row0 + ty * 8 + ri * 2 + p;
            if (grow < M) {
                float c[8];
                #pragma unroll
                for (int j = 0; j < 8; ++j) {
                    int col = (j < 4) ? (tx * 4 + j) : (64 + tx * 4 + j - 4);
                    float val = (p == 0 ? lo[j] : hi[j]) + s_bias[col];
                    c[j] = val;
                    lsum += val;
                    lsq  += val * val;
                }
                *(float4*)(Y + (long long)grow * D + tx * 4)      = make_float4(c[0], c[1], c[2], c[3]);
                *(float4*)(Y + (long long)grow * D + 64 + tx * 4) = make_float4(c[4], c[5], c[6], c[7]);
            }
        }
    }
    #pragma unroll
    for (int o = 16; o > 0; o >>= 1) {
        lsum += __shfl_down_sync(0xffffffffu, lsum, o);
        lsq  += __shfl_down_sync(0xffffffffu, lsq, o);
    }
    if ((t & 31) == 0) {
        atomicAdd(&g_sum[sidx_out],   (double)lsum);
        atomicAdd(&g_sumsq[sidx_out], (double)lsq);
    }
}

// out = relu(graph_layernorm(Y)), sums at index 2.
__global__ void k_apply_out(const float* __restrict__ Y, const float* __restrict__ w,
                            const float* __restrict__ b, float* __restrict__ out) {
    long long i = blockIdx.x * (long long)blockDim.x + threadIdx.x;
    if (i >= NELEM/4) return;
    double m = g_sum[2] * (1.0 / (double)NELEM);
    double v = g_sumsq[2] * (1.0 / (double)NELEM) - m * m;
    if (v < 0.0) v = 0.0;
    float mu  = (float)m;
    float inv = 1.0f / (sqrtf((float)v) + 1e-5f);
    int k = ((int)i * 4) & 127;
    float4 val = __ldg((const float4*)Y + i);
    float4 o;
    o.x = fmaxf((val.x - mu) * inv * __ldg(w + k + 0) + __ldg(b + k + 0), 0.f);
    o.y = fmaxf((val.y - mu) * inv * __ldg(w + k + 1) + __ldg(b + k + 1), 0.f);
    o.z = fmaxf((val.z - mu) * inv * __ldg(w + k + 2) + __ldg(b + k + 2), 0.f);
    o.w = fmaxf((val.w - mu) * inv * __ldg(w + k + 3) + __ldg(b + k + 3), 0.f);
    ((float4*)out)[i] = o;
}

extern "C" void kernel_launch(void* const* d_in, const int* in_sizes, int n_in,
                              void* d_out, int out_size) {
    const float* node = (const float*)d_in[0];
    const int*   ei   = (const int*)d_in[1];
    const float* eps  = (const float*)d_in[4];
    const float* W1   = (const float*)d_in[5];
    const float* b1   = (const float*)d_in[6];
    const float* ln1w = (const float*)d_in[7];
    const float* ln1b = (const float*)d_in[8];
    const float* W2   = (const float*)d_in[9];
    const float* b2   = (const float*)d_in[10];
    const float* ln2w = (const float*)d_in[11];
    const float* ln2b = (const float*)d_in[12];
    const float* W3   = (const float*)d_in[13];
    const float* b3   = (const float*)d_in[14];
    const float* lnow = (const float*)d_in[15];
    const float* lnob = (const float*)d_in[16];

    int E = in_sizes[1] / 2;

    void *p0, *p1;
    cudaGetSymbolAddress(&p0, g_buf0);
    cudaGetSymbolAddress(&p1, g_buf1);
    float* buf0 = (float*)p0;
    float* buf1 = (float*)p1;

    // CSR build
    k_zero<<<(NND + 1024) / 1024, 1024>>>();
    k_count<<<(E + 255) / 256, 256>>>(ei, E);
    k_scan1<<<NBLK, 1024>>>();
    k_scan2<<<1, 128>>>();
    k_scan3<<<(NND + 255) / 256, 256>>>(E);
    k_fill<<<(E + 255) / 256, 256>>>(ei, E);

    // Aggregation: h = (1+eps)*node + gather-sum
    k_aggr<<<(NND * 32 + 255) / 256, 256>>>(node, eps, buf0);

    int gblocks = (NND + 127) / 128;
    k_gemm<false><<<gblocks, 256>>>(buf0, W1, b1, nullptr, nullptr, 0, 0, buf1, NND);
    k_gemm<true> <<<gblocks, 256>>>(buf1, W2, b2, ln1w, ln1b, 0, 1, buf0, NND);
    k_gemm<true> <<<gblocks, 256>>>(buf0, W3, b3, ln2w, ln2b, 1, 2, buf1, NND);

    int nb_elem = (NELEM/4 + 255) / 256;
    k_apply_out<<<nb_elem, 256>>>(buf1, lnow, lnob, (float*)d_out);
}

// round 7
// speedup vs baseline: 2.3620x; 1.2157x over previous
#include <cuda_runtime.h>
#include <cuda_bf16.h>
#include <math.h>
#include <stdint.h>

#define NND 100000
#define D 128
#define NELEM (NND*D)
#define EMAX 2000000
#define NBLK 98           // ceil(100000/1024)

// Scratch (allocation-free)
__device__ float  g_buf0[NELEM];
__device__ float  g_buf1[NELEM];
__device__ double g_sum[3];
__device__ double g_sumsq[3];
__device__ int    g_deg[NND + 1];
__device__ int    g_off[NND + 1];
__device__ int    g_cursor[NND];
__device__ int    g_srcs[EMAX];
__device__ int    g_blocksum[128];
__device__ int    g_blockoff[128];
// bf16 hi/lo images of the three weight matrices, [k][n] row-major (no transpose).
__device__ __nv_bfloat16 g_wimg[3][2][16384];

__device__ __forceinline__ uint32_t smem_u32(const void* p) {
    uint32_t a;
    asm("{ .reg .u64 t; cvta.to.shared.u64 t, %1; cvt.u32.u64 %0, t; }" : "=r"(a) : "l"(p));
    return a;
}

__device__ __forceinline__ void ldsm_x4(uint32_t* r, uint32_t addr) {
    asm volatile("ldmatrix.sync.aligned.m8n8.x4.shared.b16 {%0,%1,%2,%3}, [%4];"
                 : "=r"(r[0]), "=r"(r[1]), "=r"(r[2]), "=r"(r[3]) : "r"(addr));
}
__device__ __forceinline__ void ldsm_x4_t(uint32_t* r, uint32_t addr) {
    asm volatile("ldmatrix.sync.aligned.m8n8.x4.trans.shared.b16 {%0,%1,%2,%3}, [%4];"
                 : "=r"(r[0]), "=r"(r[1]), "=r"(r[2]), "=r"(r[3]) : "r"(addr));
}
__device__ __forceinline__ void mma_bf16(float* d, const uint32_t* a, const uint32_t* b) {
    asm volatile(
        "mma.sync.aligned.m16n8k16.row.col.f32.bf16.bf16.f32 "
        "{%0,%1,%2,%3}, {%4,%5,%6,%7}, {%8,%9}, {%0,%1,%2,%3};"
        : "+f"(d[0]), "+f"(d[1]), "+f"(d[2]), "+f"(d[3])
        : "r"(a[0]), "r"(a[1]), "r"(a[2]), "r"(a[3]), "r"(b[0]), "r"(b[1]));
}

// smem layout (byte offsets); A rows padded to 72 bf16 (144B), B rows to 136 (272B)
#define LDA_B 144
#define LDB_B 272
#define SM_BIAS 0
#define SM_LNW  512
#define SM_LNB  1024
#define SM_AHI  1536
#define SM_ALO  (SM_AHI + 128*LDA_B)      // 1536 + 18432 = 19968
#define SM_BHI  (SM_ALO + 128*LDA_B)      // 38400
#define SM_BLO  (SM_BHI + 64*LDB_B)       // 55808
#define SM_END  (SM_BLO + 64*LDB_B)       // 73216
#define DSMEM_BYTES SM_END

// ---------------- CSR build (proven) ----------------

__global__ void k_zero() {
    int i = blockIdx.x * blockDim.x + threadIdx.x;
    if (i <= NND) g_deg[i] = 0;
    if (i < 3) { g_sum[i] = 0.0; g_sumsq[i] = 0.0; }
}

__global__ void k_count(const int* __restrict__ ei, int E) {
    int e = blockIdx.x * blockDim.x + threadIdx.x;
    if (e < E) atomicAdd(&g_deg[__ldg(ei + E + e)], 1);
}

__global__ void __launch_bounds__(1024) k_scan1() {
    __shared__ int s[1024];
    int t = threadIdx.x;
    int i = blockIdx.x * 1024 + t;
    int v = (i < NND) ? g_deg[i] : 0;
    s[t] = v;
    __syncthreads();
    #pragma unroll
    for (int o = 1; o < 1024; o <<= 1) {
        int add = (t >= o) ? s[t - o] : 0;
        __syncthreads();
        s[t] += add;
        __syncthreads();
    }
    if (i <= NND) g_off[i] = s[t] - v;
    if (t == 1023) g_blocksum[blockIdx.x] = s[t];
}

__global__ void __launch_bounds__(128) k_scan2() {
    __shared__ int s[128];
    int t = threadIdx.x;
    int v = (t < NBLK) ? g_blocksum[t] : 0;
    s[t] = v;
    __syncthreads();
    #pragma unroll
    for (int o = 1; o < 128; o <<= 1) {
        int add = (t >= o) ? s[t - o] : 0;
        __syncthreads();
        s[t] += add;
        __syncthreads();
    }
    g_blockoff[t] = s[t] - v;
}

__global__ void k_scan3(int E) {
    int i = blockIdx.x * blockDim.x + threadIdx.x;
    if (i < NND) {
        int off = g_off[i] + g_blockoff[i >> 10];
        g_off[i] = off;
        g_cursor[i] = off;
    }
    if (i == 0) g_off[NND] = E;
}

__global__ void k_fill(const int* __restrict__ ei, int E) {
    int e = blockIdx.x * blockDim.x + threadIdx.x;
    if (e >= E) return;
    int dst = __ldg(ei + E + e);
    int src = __ldg(ei + e);
    int pos = atomicAdd(&g_cursor[dst], 1);
    g_srcs[pos] = src;
}

__global__ void __launch_bounds__(256) k_aggr(const float* __restrict__ node,
                                              const float* __restrict__ eps_p,
                                              float* __restrict__ h) {
    int warp = (blockIdx.x * blockDim.x + threadIdx.x) >> 5;
    int lane = threadIdx.x & 31;
    if (warp >= NND) return;
    int n = warp;
    float s = 1.0f + __ldg(eps_p);
    const float4* nodes = (const float4*)node;
    float4 acc = __ldg(nodes + (long long)n * 32 + lane);
    acc.x *= s; acc.y *= s; acc.z *= s; acc.w *= s;
    int j   = g_off[n];
    int end = g_off[n + 1];
    for (; j + 4 <= end; j += 4) {
        int s0 = __ldg(&g_srcs[j + 0]);
        int s1 = __ldg(&g_srcs[j + 1]);
        int s2 = __ldg(&g_srcs[j + 2]);
        int s3 = __ldg(&g_srcs[j + 3]);
        float4 v0 = __ldg(nodes + (long long)s0 * 32 + lane);
        float4 v1 = __ldg(nodes + (long long)s1 * 32 + lane);
        float4 v2 = __ldg(nodes + (long long)s2 * 32 + lane);
        float4 v3 = __ldg(nodes + (long long)s3 * 32 + lane);
        acc.x += v0.x + v1.x + v2.x + v3.x;
        acc.y += v0.y + v1.y + v2.y + v3.y;
        acc.z += v0.z + v1.z + v2.z + v3.z;
        acc.w += v0.w + v1.w + v2.w + v3.w;
    }
    for (; j < end; ++j) {
        int s0 = __ldg(&g_srcs[j]);
        float4 v0 = __ldg(nodes + (long long)s0 * 32 + lane);
        acc.x += v0.x; acc.y += v0.y; acc.z += v0.z; acc.w += v0.w;
    }
    ((float4*)h)[(long long)n * 32 + lane] = acc;
}

// ---------------- Weight prep: fp32 -> bf16 hi/lo, [k][n] straight copy ----------------

__global__ void k_prepw(const float* __restrict__ W,
                        __nv_bfloat16* __restrict__ hi, __nv_bfloat16* __restrict__ lo) {
    int idx = blockIdx.x * blockDim.x + threadIdx.x;
    if (idx >= 16384) return;
    float w = __ldg(W + idx);
    __nv_bfloat16 h = __float2bfloat16_rn(w);
    float l = w - __bfloat162float(h);
    hi[idx] = h;
    lo[idx] = __float2bfloat16_rn(l);
}

// ---------------- warp-MMA bf16x3 GEMM ----------------
// Y = op(A) @ W + bias ; op = identity or relu(graph_ln(A)).
// CTA: 128x128 tile, 512 threads (16 warps, 4x4 grid, 32x32 warp tile),
// K in two 64-wide smem chunks. D = AhiBhi + AhiBlo + AloBhi.
template<bool APPLY>
__global__ void __launch_bounds__(512)
k_gemm_mma(const float* __restrict__ A,
           const __nv_bfloat16* __restrict__ whi, const __nv_bfloat16* __restrict__ wlo,
           const float* __restrict__ bias,
           const float* __restrict__ lnw, const float* __restrict__ lnb,
           int sidx_in, int sidx_out,
           float* __restrict__ Y, int M)
{
    extern __shared__ char sm[];
    const uint32_t sb = smem_u32(sm);
    const int t    = threadIdx.x;
    const int wid  = t >> 5;
    const int lane = t & 31;
    const int row0 = blockIdx.x * 128;
    const int wm   = wid & 3;        // 32-row band
    const int wn   = wid >> 2;       // 32-col band

    float* s_bias = (float*)(sm + SM_BIAS);
    float* s_lnw  = (float*)(sm + SM_LNW);
    float* s_lnb  = (float*)(sm + SM_LNB);
    if (t < 128) {
        s_bias[t] = bias[t];
        if (APPLY) { s_lnw[t] = lnw[t]; s_lnb[t] = lnb[t]; }
    }
    float mu = 0.f, inv = 0.f;
    if (APPLY) {
        double m = g_sum[sidx_in] * (1.0 / (double)NELEM);
        double v = g_sumsq[sidx_in] * (1.0 / (double)NELEM) - m * m;
        if (v < 0.0) v = 0.0;
        mu  = (float)m;
        inv = 1.0f / (sqrtf((float)v) + 1e-5f);
    }
    __syncthreads();

    float acc[2][4][4];
    #pragma unroll
    for (int i = 0; i < 2; ++i)
        #pragma unroll
        for (int j = 0; j < 4; ++j)
            #pragma unroll
            for (int q = 0; q < 4; ++q) acc[i][j][q] = 0.f;

    #pragma unroll
    for (int kc = 0; kc < 2; ++kc) {
        if (kc) __syncthreads();   // all warps done with previous chunk's smem

        // A chunk: 128 rows x 64 k, fp32 -> LN/ReLU -> bf16 hi/lo split.
        #pragma unroll
        for (int it = 0; it < 4; ++it) {
            int idx = t + it * 512;          // 0..2047 float4 units
            int r   = idx >> 4;              // tile row
            int kl  = (idx & 15) * 4;        // k within chunk
            int grow = row0 + r;
            float4 v = make_float4(0.f, 0.f, 0.f, 0.f);
            if (grow < M) v = __ldg((const float4*)(A + (long long)grow * D + kc * 64 + kl));
            if (APPLY) {
                int k0 = kc * 64 + kl;
                v.x = fmaxf((v.x - mu) * inv * s_lnw[k0+0] + s_lnb[k0+0], 0.f);
                v.y = fmaxf((v.y - mu) * inv * s_lnw[k0+1] + s_lnb[k0+1], 0.f);
                v.z = fmaxf((v.z - mu) * inv * s_lnw[k0+2] + s_lnb[k0+2], 0.f);
                v.w = fmaxf((v.w - mu) * inv * s_lnw[k0+3] + s_lnb[k0+3], 0.f);
            }
            __nv_bfloat162 h01 = __float22bfloat162_rn(make_float2(v.x, v.y));
            __nv_bfloat162 h23 = __float22bfloat162_rn(make_float2(v.z, v.w));
            float2 hf01 = __bfloat1622float2(h01);
            float2 hf23 = __bfloat1622float2(h23);
            __nv_bfloat162 l01 = __float22bfloat162_rn(make_float2(v.x - hf01.x, v.y - hf01.y));
            __nv_bfloat162 l23 = __float22bfloat162_rn(make_float2(v.z - hf23.x, v.w - hf23.y));
            uint32_t off = r * LDA_B + kl * 2;
            *(uint2*)(sm + SM_AHI + off) = make_uint2(*(uint32_t*)&h01, *(uint32_t*)&h23);
            *(uint2*)(sm + SM_ALO + off) = make_uint2(*(uint32_t*)&l01, *(uint32_t*)&l23);
        }

        // B chunk: 64 k-rows x 128 n, bf16 hi/lo straight copy.
        #pragma unroll
        for (int it = 0; it < 2; ++it) {
            int idx  = t + it * 512;         // 0..1023 uint4 units
            int kr   = idx >> 4;             // k-row within chunk
            int ncol = (idx & 15) * 8;
            uint32_t soff = kr * LDB_B + ncol * 2;
            long long goff = (long long)(kc * 64 + kr) * 128 + ncol;
            *(uint4*)(sm + SM_BHI + soff) = __ldg((const uint4*)(whi + goff));
            *(uint4*)(sm + SM_BLO + soff) = __ldg((const uint4*)(wlo + goff));
        }
        __syncthreads();

        // 4 k16 steps
        #pragma unroll
        for (int ks = 0; ks < 4; ++ks) {
            int kk = ks * 16;
            // A fragments (hi/lo, two m16 tiles)
            uint32_t Ah[2][4], Al[2][4];
            {
                int arow = 32 * wm + (lane & 15);
                int acol = kk + 8 * (lane >> 4);
                uint32_t ao = sb + SM_AHI + arow * LDA_B + acol * 2;
                ldsm_x4(Ah[0], ao);
                ldsm_x4(Ah[1], ao + 16 * LDA_B);
                uint32_t aol = ao + (SM_ALO - SM_AHI);
                ldsm_x4(Al[0], aol);
                ldsm_x4(Al[1], aol + 16 * LDA_B);
            }
            #pragma unroll
            for (int p = 0; p < 2; ++p) {     // pairs of n8 tiles
                int g  = lane >> 3;
                int l8 = lane & 7;
                int brow = kk + (g & 1) * 8 + l8;
                int bcol = 32 * wn + p * 16 + (g >> 1) * 8;
                uint32_t bo = sb + SM_BHI + brow * LDB_B + bcol * 2;
                uint32_t Bh[4], Bl[4];
                ldsm_x4_t(Bh, bo);
                ldsm_x4_t(Bl, bo + (SM_BLO - SM_BHI));
                #pragma unroll
                for (int mt = 0; mt < 2; ++mt) {
                    mma_bf16(acc[mt][2*p],   Ah[mt], Bh);
                    mma_bf16(acc[mt][2*p+1], Ah[mt], Bh + 2);
                    mma_bf16(acc[mt][2*p],   Ah[mt], Bl);
                    mma_bf16(acc[mt][2*p+1], Ah[mt], Bl + 2);
                    mma_bf16(acc[mt][2*p],   Al[mt], Bh);
                    mma_bf16(acc[mt][2*p+1], Al[mt], Bh + 2);
                }
            }
        }
    }

    // Epilogue: bias, store, LN partial sums.
    float lsum = 0.f, lsq = 0.f;
    #pragma unroll
    for (int mt = 0; mt < 2; ++mt) {
        #pragma unroll
        for (int nt = 0; nt < 4; ++nt) {
            int r = row0 + 32 * wm + 16 * mt + (lane >> 2);
            int c = 32 * wn + 8 * nt + 2 * (lane & 3);
            float b0 = s_bias[c], b1 = s_bias[c + 1];
            if (r < M) {
                float2 v = make_float2(acc[mt][nt][0] + b0, acc[mt][nt][1] + b1);
                lsum += v.x + v.y;
                lsq  += v.x * v.x + v.y * v.y;
                *(float2*)(Y + (long long)r * D + c) = v;
            }
            if (r + 8 < M) {
                float2 v = make_float2(acc[mt][nt][2] + b0, acc[mt][nt][3] + b1);
                lsum += v.x + v.y;
                lsq  += v.x * v.x + v.y * v.y;
                *(float2*)(Y + (long long)(r + 8) * D + c) = v;
            }
        }
    }
    #pragma unroll
    for (int o = 16; o > 0; o >>= 1) {
        lsum += __shfl_down_sync(0xffffffffu, lsum, o);
        lsq  += __shfl_down_sync(0xffffffffu, lsq, o);
    }
    if (lane == 0) {
        atomicAdd(&g_sum[sidx_out],   (double)lsum);
        atomicAdd(&g_sumsq[sidx_out], (double)lsq);
    }
}

// out = relu(graph_layernorm(Y)), sums at index 2.
__global__ void k_apply_out(const float* __restrict__ Y, const float* __restrict__ w,
                            const float* __restrict__ b, float* __restrict__ out) {
    long long i = blockIdx.x * (long long)blockDim.x + threadIdx.x;
    if (i >= NELEM/4) return;
    double m = g_sum[2] * (1.0 / (double)NELEM);
    double v = g_sumsq[2] * (1.0 / (double)NELEM) - m * m;
    if (v < 0.0) v = 0.0;
    float mu  = (float)m;
    float inv = 1.0f / (sqrtf((float)v) + 1e-5f);
    int k = ((int)i * 4) & 127;
    float4 val = __ldg((const float4*)Y + i);
    float4 o;
    o.x = fmaxf((val.x - mu) * inv * __ldg(w + k + 0) + __ldg(b + k + 0), 0.f);
    o.y = fmaxf((val.y - mu) * inv * __ldg(w + k + 1) + __ldg(b + k + 1), 0.f);
    o.z = fmaxf((val.z - mu) * inv * __ldg(w + k + 2) + __ldg(b + k + 2), 0.f);
    o.w = fmaxf((val.w - mu) * inv * __ldg(w + k + 3) + __ldg(b + k + 3), 0.f);
    ((float4*)out)[i] = o;
}

extern "C" void kernel_launch(void* const* d_in, const int* in_sizes, int n_in,
                              void* d_out, int out_size) {
    const float* node = (const float*)d_in[0];
    const int*   ei   = (const int*)d_in[1];
    const float* eps  = (const float*)d_in[4];
    const float* W1   = (const float*)d_in[5];
    const float* b1   = (const float*)d_in[6];
    const float* ln1w = (const float*)d_in[7];
    const float* ln1b = (const float*)d_in[8];
    const float* W2   = (const float*)d_in[9];
    const float* b2   = (const float*)d_in[10];
    const float* ln2w = (const float*)d_in[11];
    const float* ln2b = (const float*)d_in[12];
    const float* W3   = (const float*)d_in[13];
    const float* b3   = (const float*)d_in[14];
    const float* lnow = (const float*)d_in[15];
    const float* lnob = (const float*)d_in[16];

    int E = in_sizes[1] / 2;

    void *p0, *p1, *pw;
    cudaGetSymbolAddress(&p0, g_buf0);
    cudaGetSymbolAddress(&p1, g_buf1);
    cudaGetSymbolAddress(&pw, g_wimg);
    float* buf0 = (float*)p0;
    float* buf1 = (float*)p1;
    __nv_bfloat16* wimg = (__nv_bfloat16*)pw;   // [3][2][16384]

    cudaFuncSetAttribute(k_gemm_mma<false>, cudaFuncAttributeMaxDynamicSharedMemorySize, DSMEM_BYTES);
    cudaFuncSetAttribute(k_gemm_mma<true>,  cudaFuncAttributeMaxDynamicSharedMemorySize, DSMEM_BYTES);

    // Weight prep (tiny, independent)
    k_prepw<<<64, 256>>>(W1, wimg + 0*32768, wimg + 0*32768 + 16384);
    k_prepw<<<64, 256>>>(W2, wimg + 1*32768, wimg + 1*32768 + 16384);
    k_prepw<<<64, 256>>>(W3, wimg + 2*32768, wimg + 2*32768 + 16384);

    // CSR build
    k_zero<<<(NND + 1024) / 1024, 1024>>>();
    k_count<<<(E + 255) / 256, 256>>>(ei, E);
    k_scan1<<<NBLK, 1024>>>();
    k_scan2<<<1, 128>>>();
    k_scan3<<<(NND + 255) / 256, 256>>>(E);
    k_fill<<<(E + 255) / 256, 256>>>(ei, E);

    // Aggregation: h = (1+eps)*node + gather-sum
    k_aggr<<<(NND * 32 + 255) / 256, 256>>>(node, eps, buf0);

    int gblocks = (NND + 127) / 128;
    k_gemm_mma<false><<<gblocks, 512, DSMEM_BYTES>>>(buf0, wimg + 0*32768, wimg + 0*32768 + 16384,
                                                     b1, nullptr, nullptr, 0, 0, buf1, NND);
    k_gemm_mma<true> <<<gblocks, 512, DSMEM_BYTES>>>(buf1, wimg + 1*32768, wimg + 1*32768 + 16384,
                                                     b2, ln1w, ln1b, 0, 1, buf0, NND);
    k_gemm_mma<true> <<<gblocks, 512, DSMEM_BYTES>>>(buf0, wimg + 2*32768, wimg + 2*32768 + 16384,
                                                     b3, ln2w, ln2b, 1, 2, buf1, NND);

    int nb_elem = (NELEM/4 + 255) / 256;
    k_apply_out<<<nb_elem, 256>>>(buf1, lnow, lnob, (float*)d_out);
}